// round 3
// baseline (speedup 1.0000x reference)
#include <cuda_runtime.h>
#include <math.h>
#include <stddef.h>

// ---------------- problem constants ----------------
#define SQv   2048
#define Dv    1024
#define Hv    16
#define DHv   64
#define NCv   4096
#define LTv   16      // tables
#define KHv   8       // hash funcs per table
#define LKv   128     // LT*KH
#define NBv   256     // buckets
#define TPPv  1024
#define SSv   1024    // sample budget
#define PPv   64

// ---------------- device scratch ----------------
__device__ __align__(16) float g_xln   [SQv*Dv];
__device__ __align__(16) float g_q     [SQv*Dv];
__device__ __align__(16) float g_k     [SQv*Dv];
__device__ __align__(16) float g_v     [SQv*Dv];
__device__ __align__(16) float g_ctx   [SQv*Dv];
__device__ __align__(16) float g_attn  [SQv*Dv];
__device__ __align__(16) float g_normed[SQv*Dv];
__device__ __align__(16) float g_projn [LKv*NCv];
__device__ __align__(16) float g_projt [LKv*TPPv];
__device__ __align__(16) float g_tanhpt[TPPv*LKv];
__device__ __align__(16) float g_tanhpns[SSv*LKv];
__device__ __align__(16) float g_w1s   [SSv*Dv];
__device__ __align__(16) float g_w2sT  [Dv*SSv];
__device__ __align__(16) float g_b1s   [SSv];
__device__ __align__(16) float g_logits[TPPv*SSv];
__device__ __align__(16) float g_acts  [TPPv*SSv];
__device__ __align__(16) float g_trip  [2*TPPv];
__device__ int g_coden[LTv*NCv];
__device__ int g_codet[LTv*TPPv];
__device__ int g_hist [LTv*NBv];
__device__ int g_score[NCv];
__device__ int g_sids [SSv];

// ---------------- helpers ----------------
__device__ __forceinline__ unsigned f2tf(float x){
    unsigned u; asm("cvt.rna.tf32.f32 %0, %1;" : "=r"(u) : "f"(x)); return u;
}
__device__ __forceinline__ void mma8(float* d, const unsigned* a, const unsigned* b){
    asm volatile("mma.sync.aligned.m16n8k8.row.col.f32.tf32.tf32.f32 "
        "{%0,%1,%2,%3},{%4,%5,%6,%7},{%8,%9},{%0,%1,%2,%3};"
        : "+f"(d[0]), "+f"(d[1]), "+f"(d[2]), "+f"(d[3])
        : "r"(a[0]), "r"(a[1]), "r"(a[2]), "r"(a[3]), "r"(b[0]), "r"(b[1]));
}
__device__ __forceinline__ float gelu_exact(float x){
    return 0.5f * x * (1.f + erff(x * 0.70710678118654752f));
}

// ---------------- LayerNorm ----------------
__global__ void ln_kernel(const float* __restrict__ x, const float* __restrict__ g,
                          const float* __restrict__ b, float* __restrict__ y)
{
    int row = blockIdx.x;
    const float* xr = x + (size_t)row * Dv;
    __shared__ float red[256];
    int tid = threadIdx.x;
    float s = 0.f, ss = 0.f;
    for (int i = tid; i < Dv; i += 256) { float v = xr[i]; s += v; ss += v * v; }
    red[tid] = s; __syncthreads();
    for (int st = 128; st > 0; st >>= 1) { if (tid < st) red[tid] += red[tid + st]; __syncthreads(); }
    float mean = red[0] / Dv;
    __syncthreads();
    red[tid] = ss; __syncthreads();
    for (int st = 128; st > 0; st >>= 1) { if (tid < st) red[tid] += red[tid + st]; __syncthreads(); }
    float var = red[0] / Dv - mean * mean;
    float inv = rsqrtf(var + 1e-12f);
    float* yr = y + (size_t)row * Dv;
    for (int i = tid; i < Dv; i += 256) yr[i] = (xr[i] - mean) * inv * g[i] + b[i];
}

// ---------------- TF32 tensor-core GEMM NT ----------------
// C[M,N] = A[M,K]*B[N,K]^T ; SPLIT=3 -> 3xTF32 (fp32-class), SPLIT=1 -> plain TF32.
// EPI==1: write C (=logits) and gelu(C) into C2.
template<int SPLIT, int EPI, bool BIAS, bool RES, int BM_, int BN_>
__global__ void __launch_bounds__(256, 1)
mma_nt(const float* __restrict__ A, const float* __restrict__ B,
       const float* __restrict__ bias, const float* __restrict__ res,
       float* __restrict__ C, float* __restrict__ C2, int M, int N, int K)
{
    constexpr int BK = 32, LD = 36;
    constexpr int WARPS_M = 2;
    constexpr int WTM = BM_ / 2, WTN = BN_ / 4;
    constexpr int MT = WTM / 16, NT = WTN / 8;
    extern __shared__ unsigned sm[];
    unsigned* Ah = sm;
    unsigned* Bh = Ah + BM_ * LD;
    unsigned* Al = (SPLIT == 3) ? Bh + BN_ * LD : Ah;
    unsigned* Bl = (SPLIT == 3) ? Al + BM_ * LD : Bh;

    const int tid = threadIdx.x;
    const int lane = tid & 31, wid = tid >> 5;
    const int wm = wid & 1, wn = wid >> 1;
    const int m0 = blockIdx.y * BM_, n0 = blockIdx.x * BN_;

    constexpr int PA = BM_ / 32;
    constexpr int PB = BN_ / 32;
    const int lrw = tid >> 3;
    const int lcc = (tid & 7) * 4;

    float4 pa[PA], pb[PB];
    float acc[MT][NT][4];
    #pragma unroll
    for (int i = 0; i < MT; i++)
        #pragma unroll
        for (int j = 0; j < NT; j++)
            #pragma unroll
            for (int u = 0; u < 4; u++) acc[i][j][u] = 0.f;

    #pragma unroll
    for (int p = 0; p < PA; p++)
        pa[p] = *(const float4*)(A + (size_t)(m0 + p*32 + lrw) * K + lcc);
    #pragma unroll
    for (int p = 0; p < PB; p++)
        pb[p] = *(const float4*)(B + (size_t)(n0 + p*32 + lrw) * K + lcc);

    const int ntiles = K / BK;
    for (int kt = 0; kt < ntiles; kt++) {
        __syncthreads();
        #pragma unroll
        for (int p = 0; p < PA; p++) {
            float vv[4] = {pa[p].x, pa[p].y, pa[p].z, pa[p].w};
            #pragma unroll
            for (int i = 0; i < 4; i++) {
                unsigned h = f2tf(vv[i]);
                Ah[(p*32 + lrw) * LD + lcc + i] = h;
                if (SPLIT == 3)
                    Al[(p*32 + lrw) * LD + lcc + i] = f2tf(vv[i] - __uint_as_float(h));
            }
        }
        #pragma unroll
        for (int p = 0; p < PB; p++) {
            float vv[4] = {pb[p].x, pb[p].y, pb[p].z, pb[p].w};
            #pragma unroll
            for (int i = 0; i < 4; i++) {
                unsigned h = f2tf(vv[i]);
                Bh[(p*32 + lrw) * LD + lcc + i] = h;
                if (SPLIT == 3)
                    Bl[(p*32 + lrw) * LD + lcc + i] = f2tf(vv[i] - __uint_as_float(h));
            }
        }
        __syncthreads();
        if (kt + 1 < ntiles) {
            const float* An = A + (size_t)(kt + 1) * BK;
            const float* Bn = B + (size_t)(kt + 1) * BK;
            #pragma unroll
            for (int p = 0; p < PA; p++)
                pa[p] = *(const float4*)(An + (size_t)(m0 + p*32 + lrw) * K + lcc);
            #pragma unroll
            for (int p = 0; p < PB; p++)
                pb[p] = *(const float4*)(Bn + (size_t)(n0 + p*32 + lrw) * K + lcc);
        }
        #pragma unroll
        for (int ks = 0; ks < 4; ks++) {
            unsigned ah[MT][4], al[MT][4], bh[NT][2], bl[NT][2];
            #pragma unroll
            for (int i = 0; i < MT; i++) {
                int r = wm * WTM + i * 16 + (lane >> 2);
                int c = ks * 8 + (lane & 3);
                ah[i][0] = Ah[r*LD + c];       ah[i][1] = Ah[(r+8)*LD + c];
                ah[i][2] = Ah[r*LD + c + 4];   ah[i][3] = Ah[(r+8)*LD + c + 4];
                if (SPLIT == 3) {
                    al[i][0] = Al[r*LD + c];     al[i][1] = Al[(r+8)*LD + c];
                    al[i][2] = Al[r*LD + c + 4]; al[i][3] = Al[(r+8)*LD + c + 4];
                }
            }
            #pragma unroll
            for (int j = 0; j < NT; j++) {
                int r = wn * WTN + j * 8 + (lane >> 2);
                int c = ks * 8 + (lane & 3);
                bh[j][0] = Bh[r*LD + c];  bh[j][1] = Bh[r*LD + c + 4];
                if (SPLIT == 3) {
                    bl[j][0] = Bl[r*LD + c];  bl[j][1] = Bl[r*LD + c + 4];
                }
            }
            #pragma unroll
            for (int i = 0; i < MT; i++)
                #pragma unroll
                for (int j = 0; j < NT; j++) {
                    mma8(acc[i][j], ah[i], bh[j]);
                    if (SPLIT == 3) {
                        mma8(acc[i][j], ah[i], bl[j]);
                        mma8(acc[i][j], al[i], bh[j]);
                    }
                }
        }
    }
    // epilogue
    #pragma unroll
    for (int i = 0; i < MT; i++) {
        #pragma unroll
        for (int j = 0; j < NT; j++) {
            int r = m0 + wm * WTM + i * 16 + (lane >> 2);
            int c = n0 + wn * WTN + j * 8 + (lane & 3) * 2;
            float v00 = acc[i][j][0], v01 = acc[i][j][1];
            float v10 = acc[i][j][2], v11 = acc[i][j][3];
            if (BIAS) { float b0 = bias[c], b1 = bias[c+1]; v00 += b0; v01 += b1; v10 += b0; v11 += b1; }
            if (RES) {
                v00 += res[(size_t)r*N + c];     v01 += res[(size_t)r*N + c + 1];
                v10 += res[(size_t)(r+8)*N + c]; v11 += res[(size_t)(r+8)*N + c + 1];
            }
            *(float2*)(C + (size_t)r*N + c)     = make_float2(v00, v01);
            *(float2*)(C + (size_t)(r+8)*N + c) = make_float2(v10, v11);
            if (EPI == 1) {
                *(float2*)(C2 + (size_t)r*N + c)     = make_float2(gelu_exact(v00), gelu_exact(v01));
                *(float2*)(C2 + (size_t)(r+8)*N + c) = make_float2(gelu_exact(v10), gelu_exact(v11));
            }
        }
    }
}

// ---------------- exact-fp32 GEMM NT (hash projections only) ----------------
template<bool HAS_BIAS>
__global__ void gemm_nt(const float* __restrict__ A, const float* __restrict__ Bm,
                        const float* __restrict__ bias,
                        float* __restrict__ C, int M, int N, int Kd)
{
    __shared__ float As[16][64];
    __shared__ float Bs[16][64];
    int tid = threadIdx.x;
    int tx = tid & 15, ty = tid >> 4;
    int m0 = blockIdx.y * 64, n0 = blockIdx.x * 64;
    float acc[4][4] = {};
    for (int k0 = 0; k0 < Kd; k0 += 16) {
        int idx = tid * 4;
        int r = idx >> 4, kk = idx & 15;
        float4 av = *(const float4*)(A  + (size_t)(m0 + r) * Kd + k0 + kk);
        As[kk+0][r] = av.x; As[kk+1][r] = av.y; As[kk+2][r] = av.z; As[kk+3][r] = av.w;
        float4 bv = *(const float4*)(Bm + (size_t)(n0 + r) * Kd + k0 + kk);
        Bs[kk+0][r] = bv.x; Bs[kk+1][r] = bv.y; Bs[kk+2][r] = bv.z; Bs[kk+3][r] = bv.w;
        __syncthreads();
        #pragma unroll
        for (int q = 0; q < 16; q++) {
            float a[4], b[4];
            #pragma unroll
            for (int i = 0; i < 4; i++) a[i] = As[q][ty*4+i];
            #pragma unroll
            for (int j = 0; j < 4; j++) b[j] = Bs[q][tx*4+j];
            #pragma unroll
            for (int i = 0; i < 4; i++)
                #pragma unroll
                for (int j = 0; j < 4; j++)
                    acc[i][j] += a[i] * b[j];
        }
        __syncthreads();
    }
    #pragma unroll
    for (int i = 0; i < 4; i++) {
        int m = m0 + ty*4 + i;
        #pragma unroll
        for (int j = 0; j < 4; j++) {
            int n = n0 + tx*4 + j;
            float v = acc[i][j];
            if (HAS_BIAS) v += bias[n];
            C[(size_t)m * N + n] = v;
        }
    }
}

// ---------------- attention (fp32, conflict-free smem) ----------------
__global__ void __launch_bounds__(256, 2)
attn2(const float* __restrict__ q, const float* __restrict__ k,
      const float* __restrict__ v, const float* __restrict__ mask,
      float* __restrict__ ctx)
{
    extern __shared__ float sa[];
    float* Qs = sa;               // 64*65
    float* Ks = Qs + 64*65;
    float* Vs = Ks + 64*65;
    float* Ps = Vs + 64*65;
    float* Ms = Ps + 64*65;       // 64
    const int tid = threadIdx.x;
    const int tx = tid & 15, ty = tid >> 4;
    const int h = blockIdx.y, q0 = blockIdx.x * 64;

    for (int idx = tid; idx < 64*16; idx += 256) {
        int r = idx >> 4, c4 = (idx & 15) * 4;
        float4 t = *(const float4*)(q + (size_t)(q0 + r) * Dv + h * 64 + c4);
        Qs[r*65 + c4] = t.x; Qs[r*65 + c4 + 1] = t.y;
        Qs[r*65 + c4 + 2] = t.z; Qs[r*65 + c4 + 3] = t.w;
    }
    float o[4][4];
    float mr[4], lrn[4];
    #pragma unroll
    for (int i = 0; i < 4; i++) {
        mr[i] = -1e30f; lrn[i] = 0.f;
        #pragma unroll
        for (int j = 0; j < 4; j++) o[i][j] = 0.f;
    }

    for (int kt = 0; kt < SQv/64; kt++) {
        int k0 = kt * 64;
        __syncthreads();
        for (int idx = tid; idx < 64*16; idx += 256) {
            int r = idx >> 4, c4 = (idx & 15) * 4;
            float4 tk = *(const float4*)(k + (size_t)(k0 + r) * Dv + h * 64 + c4);
            Ks[r*65 + c4] = tk.x; Ks[r*65 + c4 + 1] = tk.y;
            Ks[r*65 + c4 + 2] = tk.z; Ks[r*65 + c4 + 3] = tk.w;
            float4 tv = *(const float4*)(v + (size_t)(k0 + r) * Dv + h * 64 + c4);
            Vs[r*65 + c4] = tv.x; Vs[r*65 + c4 + 1] = tv.y;
            Vs[r*65 + c4 + 2] = tv.z; Vs[r*65 + c4 + 3] = tv.w;
        }
        if (tid < 64) Ms[tid] = -1000.f * (1.f - mask[k0 + tid]);
        __syncthreads();

        float s[4][4];
        #pragma unroll
        for (int i = 0; i < 4; i++)
            #pragma unroll
            for (int j = 0; j < 4; j++) s[i][j] = 0.f;
        #pragma unroll
        for (int d = 0; d < 64; d++) {
            float a[4], b[4];
            #pragma unroll
            for (int i = 0; i < 4; i++) a[i] = Qs[(ty + 16*i)*65 + d];
            #pragma unroll
            for (int j = 0; j < 4; j++) b[j] = Ks[(tx + 16*j)*65 + d];
            #pragma unroll
            for (int i = 0; i < 4; i++)
                #pragma unroll
                for (int j = 0; j < 4; j++) s[i][j] += a[i] * b[j];
        }
        float msr[4];
        #pragma unroll
        for (int j = 0; j < 4; j++) msr[j] = Ms[tx + 16*j];
        #pragma unroll
        for (int i = 0; i < 4; i++) {
            float mx = -1e30f;
            #pragma unroll
            for (int j = 0; j < 4; j++) {
                s[i][j] = s[i][j] * 0.125f + msr[j];
                mx = fmaxf(mx, s[i][j]);
            }
            #pragma unroll
            for (int off = 8; off > 0; off >>= 1)
                mx = fmaxf(mx, __shfl_xor_sync(0xffffffffu, mx, off));
            float mnew = fmaxf(mr[i], mx);
            float al = expf(mr[i] - mnew);
            float ps = 0.f;
            #pragma unroll
            for (int j = 0; j < 4; j++) {
                float p = expf(s[i][j] - mnew);
                Ps[(ty + 16*i)*65 + tx + 16*j] = p;
                ps += p;
            }
            #pragma unroll
            for (int off = 8; off > 0; off >>= 1)
                ps += __shfl_xor_sync(0xffffffffu, ps, off);
            lrn[i] = lrn[i] * al + ps;
            mr[i] = mnew;
            #pragma unroll
            for (int j = 0; j < 4; j++) o[i][j] *= al;
        }
        __syncthreads();
        #pragma unroll
        for (int kk = 0; kk < 64; kk++) {
            float a[4], b[4];
            #pragma unroll
            for (int i = 0; i < 4; i++) a[i] = Ps[(ty + 16*i)*65 + kk];
            #pragma unroll
            for (int j = 0; j < 4; j++) b[j] = Vs[kk*65 + tx + 16*j];
            #pragma unroll
            for (int i = 0; i < 4; i++)
                #pragma unroll
                for (int j = 0; j < 4; j++) o[i][j] += a[i] * b[j];
        }
    }
    #pragma unroll
    for (int i = 0; i < 4; i++) {
        float inv = 1.f / lrn[i];
        #pragma unroll
        for (int j = 0; j < 4; j++)
            ctx[(size_t)(q0 + ty + 16*i) * Dv + h * 64 + tx + 16*j] = o[i][j] * inv;
    }
}

// ---------------- SimHash codes ----------------
__global__ void coden_kernel()
{
    int idx = blockIdx.x * 256 + threadIdx.x;
    if (idx >= LTv * NCv) return;
    int n = idx & (NCv - 1), l = idx >> 12;
    int code = 0;
    #pragma unroll
    for (int kk = 0; kk < KHv; kk++)
        if (g_projn[(size_t)(l * KHv + kk) * NCv + n] > 0.f) code |= (1 << kk);
    g_coden[l * NCv + n] = code;
}
__global__ void codet_kernel()
{
    int idx = blockIdx.x * 256 + threadIdx.x;
    if (idx >= LTv * TPPv) return;
    int t = idx & (TPPv - 1), l = idx >> 10;
    int code = 0;
    #pragma unroll
    for (int kk = 0; kk < KHv; kk++)
        if (g_projt[(size_t)(l * KHv + kk) * TPPv + t] > 0.f) code |= (1 << kk);
    g_codet[l * TPPv + t] = code;
}
__global__ void tanhpt_kernel()
{
    int idx = blockIdx.x * 256 + threadIdx.x;
    if (idx >= TPPv * LKv) return;
    int t = idx >> 7, lk = idx & 127;
    g_tanhpt[idx] = tanhf(g_projt[(size_t)lk * TPPv + t]);
}

// ---------------- histogram + score ----------------
__global__ void hist_zero()
{
    int i = blockIdx.x * 256 + threadIdx.x;
    if (i < LTv * NBv) g_hist[i] = 0;
}
__global__ void hist_build()
{
    int idx = blockIdx.x * 256 + threadIdx.x;
    if (idx >= LTv * TPPv) return;
    int t = idx & (TPPv - 1), l = idx >> 10;
    atomicAdd(&g_hist[l * NBv + g_codet[l * TPPv + t]], 1);
}
__global__ void score_kernel()
{
    int n = blockIdx.x * 256 + threadIdx.x;
    if (n >= NCv) return;
    int s = 0;
    #pragma unroll
    for (int l = 0; l < LTv; l++) s += g_hist[l * NBv + g_coden[l * NCv + n]];
    g_score[n] = s;
}

// ---------------- stable top-S selection ----------------
__global__ void select_kernel()
{
    __shared__ int ssc[NCv];
    __shared__ int red[1024];
    int tid = threadIdx.x;
    for (int i = tid; i < NCv; i += 1024) ssc[i] = g_score[i];
    __syncthreads();

    int lo = 0, hi = LTv * TPPv + 1;
    while (lo + 1 < hi) {
        int mid = (lo + hi) >> 1;
        int c = 0;
        for (int i = tid; i < NCv; i += 1024) c += (ssc[i] >= mid);
        red[tid] = c; __syncthreads();
        for (int st = 512; st > 0; st >>= 1) { if (tid < st) red[tid] += red[tid + st]; __syncthreads(); }
        int tot = red[0]; __syncthreads();
        if (tot >= SSv) lo = mid; else hi = mid;
    }
    int tau = lo;
    int c = 0;
    for (int i = tid; i < NCv; i += 1024) c += (ssc[i] > tau);
    red[tid] = c; __syncthreads();
    for (int st = 512; st > 0; st >>= 1) { if (tid < st) red[tid] += red[tid + st]; __syncthreads(); }
    int m = red[0];
    int need = SSv - m;
    __syncthreads();

    int base = tid * 4;
    int gtp[4], eqp[4];
    int lgt = 0, leq = 0;
    #pragma unroll
    for (int j = 0; j < 4; j++) {
        int sc = ssc[base + j];
        gtp[j] = lgt; eqp[j] = leq;
        lgt += (sc > tau); leq += (sc == tau);
    }
    red[tid] = (lgt << 16) | leq; __syncthreads();
    for (int off = 1; off < 1024; off <<= 1) {
        int vv = (tid >= off) ? red[tid - off] : 0;
        __syncthreads();
        red[tid] += vv;
        __syncthreads();
    }
    int excl = (tid == 0) ? 0 : red[tid - 1];
    int egt = excl >> 16, eeq = excl & 0xffff;
    #pragma unroll
    for (int j = 0; j < 4; j++) {
        int sc = ssc[base + j];
        if (sc > tau)                                g_sids[egt + gtp[j]] = base + j;
        else if (sc == tau && (eeq + eqp[j]) < need) g_sids[m + eeq + eqp[j]] = base + j;
    }
}

// ---------------- gathers ----------------
__global__ void gather_kernel(const float* __restrict__ W1, const float* __restrict__ b1)
{
    int idx = blockIdx.x * 256 + threadIdx.x;
    if (idx >= SSv * Dv) return;
    int s = idx >> 10, dcol = idx & 1023;
    int row = g_sids[s];
    g_w1s[idx] = W1[(size_t)row * Dv + dcol];
    if (dcol == 0) g_b1s[s] = b1[row];
}
__global__ void gatherT_kernel(const float* __restrict__ W2)
{
    __shared__ float tile[32][33];
    int s0 = blockIdx.x * 32, d0 = blockIdx.y * 32;
    int tx = threadIdx.x & 31, ty8 = threadIdx.x >> 5;
    for (int r = ty8; r < 32; r += 8) {
        int row = g_sids[s0 + r];
        tile[r][tx] = W2[(size_t)row * Dv + d0 + tx];
    }
    __syncthreads();
    for (int r = ty8; r < 32; r += 8)
        g_w2sT[(size_t)(d0 + r) * SSv + s0 + tx] = tile[tx][r];
}
__global__ void tanhpns_kernel()
{
    int idx = blockIdx.x * 256 + threadIdx.x;
    if (idx >= SSv * LKv) return;
    int s = idx >> 7, lk = idx & 127;
    g_tanhpns[idx] = tanhf(g_projn[(size_t)lk * NCv + g_sids[s]]);
}

// ---------------- triplet loss (warp per token, shuffle-only) ----------------
__global__ void __launch_bounds__(256)
triplet2(int chunk)
{
    __shared__ float vals[8][1024];
    int w = threadIdx.x >> 5, lane = threadIdx.x & 31;
    int t = blockIdx.x * 8 + w;
    const float* lrow = g_logits + (size_t)t * SSv;

    float apos = 0.f, aneg = 0.f;
    for (int phase = 0; phase < 2; phase++) {
        for (int i = lane; i < 256; i += 32)
            ((float4*)vals[w])[i] = ((const float4*)lrow)[i];
        __syncwarp();
        float sv[4] = {0.f, 0.f, 0.f, 0.f};
        for (int it = 0; it < PPv; it++) {
            float bv = (phase == 0) ? -1e30f : 1e30f;
            int bi = 1 << 30;
            #pragma unroll
            for (int qd = 0; qd < 32; qd++) {
                int i = lane + (qd << 5);
                float x = vals[w][i];
                bool better = (phase == 0) ? (x > bv) : (x < bv);
                if (better) { bv = x; bi = i; }
            }
            #pragma unroll
            for (int off = 16; off > 0; off >>= 1) {
                float ov = __shfl_xor_sync(0xffffffffu, bv, off);
                int   oi = __shfl_xor_sync(0xffffffffu, bi, off);
                bool take = (phase == 0)
                    ? (ov > bv || (ov == bv && oi < bi))
                    : (ov < bv || (ov == bv && oi < bi));
                if (take) { bv = ov; bi = oi; }
            }
            #pragma unroll
            for (int c2 = 0; c2 < 4; c2++)
                sv[c2] += g_tanhpns[(size_t)bi * LKv + lane + 32 * c2];
            if (lane == 0) vals[w][bi] = (phase == 0) ? -1e30f : 1e30f;
            __syncwarp();
        }
        float a = 0.f;
        #pragma unroll
        for (int c2 = 0; c2 < 4; c2++)
            a += sv[c2] * g_tanhpt[(size_t)t * LKv + lane + 32 * c2];
        #pragma unroll
        for (int off = 16; off > 0; off >>= 1)
            a += __shfl_xor_sync(0xffffffffu, a, off);
        a *= 1.0f / (128.0f * 64.0f);
        if (phase == 0) apos = a; else aneg = a;
    }
    if (lane == 0) g_trip[chunk * TPPv + t] = fmaxf(aneg - apos + 0.5f, 0.f);
}

__global__ void trip_reduce(float* __restrict__ outp)
{
    __shared__ float red[1024];
    int tid = threadIdx.x;
    red[tid] = g_trip[tid] + g_trip[tid + 1024];
    __syncthreads();
    for (int st = 512; st > 0; st >>= 1) { if (tid < st) red[tid] += red[tid + st]; __syncthreads(); }
    if (tid == 0) *outp = red[0] * (1.0f / 2048.0f);
}

// ---------------- host ----------------
extern "C" void kernel_launch(void* const* d_in, const int* in_sizes, int n_in,
                              void* d_out, int out_size)
{
    const float* hidden = (const float*)d_in[0];
    const float* amask  = (const float*)d_in[1];
    const float* ln1_g  = (const float*)d_in[2];
    const float* ln1_b  = (const float*)d_in[3];
    const float* Wq     = (const float*)d_in[4];
    const float* bq     = (const float*)d_in[5];
    const float* Wk     = (const float*)d_in[6];
    const float* bk     = (const float*)d_in[7];
    const float* Wv     = (const float*)d_in[8];
    const float* bv     = (const float*)d_in[9];
    const float* Wo     = (const float*)d_in[10];
    const float* bo     = (const float*)d_in[11];
    const float* ln2_g  = (const float*)d_in[12];
    const float* ln2_b  = (const float*)d_in[13];
    const float* W1     = (const float*)d_in[14];
    const float* b1     = (const float*)d_in[15];
    const float* Whash  = (const float*)d_in[16];
    const float* W2     = (const float*)d_in[17];
    const float* b2     = (const float*)d_in[18];
    float* out = (float*)d_out;

    float *xln, *q, *k, *v, *ctx, *attn, *normed, *projn, *projt;
    float *w1s, *w2sT, *b1s, *logits, *acts;
    cudaGetSymbolAddress((void**)&xln,    g_xln);
    cudaGetSymbolAddress((void**)&q,      g_q);
    cudaGetSymbolAddress((void**)&k,      g_k);
    cudaGetSymbolAddress((void**)&v,      g_v);
    cudaGetSymbolAddress((void**)&ctx,    g_ctx);
    cudaGetSymbolAddress((void**)&attn,   g_attn);
    cudaGetSymbolAddress((void**)&normed, g_normed);
    cudaGetSymbolAddress((void**)&projn,  g_projn);
    cudaGetSymbolAddress((void**)&projt,  g_projt);
    cudaGetSymbolAddress((void**)&w1s,    g_w1s);
    cudaGetSymbolAddress((void**)&w2sT,   g_w2sT);
    cudaGetSymbolAddress((void**)&b1s,    g_b1s);
    cudaGetSymbolAddress((void**)&logits, g_logits);
    cudaGetSymbolAddress((void**)&acts,   g_acts);

    // dynamic smem opt-in
    const int SM3  = (128 + 128) * 36 * 4 * 2;   // 73728
    const int SM1  = (64 + 128) * 36 * 4;        // 27648
    const int SMAT = (4 * 64 * 65 + 64) * 4;     // 66816
    cudaFuncSetAttribute((const void*)mma_nt<3,0,true,false,128,128>,
                         cudaFuncAttributeMaxDynamicSharedMemorySize, SM3);
    cudaFuncSetAttribute((const void*)mma_nt<3,0,true,true,128,128>,
                         cudaFuncAttributeMaxDynamicSharedMemorySize, SM3);
    cudaFuncSetAttribute((const void*)mma_nt<1,1,true,false,64,128>,
                         cudaFuncAttributeMaxDynamicSharedMemorySize, SM1);
    cudaFuncSetAttribute((const void*)mma_nt<1,0,true,true,64,128>,
                         cudaFuncAttributeMaxDynamicSharedMemorySize, SM1);
    cudaFuncSetAttribute((const void*)attn2,
                         cudaFuncAttributeMaxDynamicSharedMemorySize, SMAT);

    // ---- attention path ----
    ln_kernel<<<SQv, 256>>>(hidden, ln1_g, ln1_b, xln);
    dim3 gA(Dv/128, SQv/128);   // (8,16)
    mma_nt<3,0,true,false,128,128><<<gA, 256, SM3>>>(xln, Wq, bq, nullptr, q,   nullptr, SQv, Dv, Dv);
    mma_nt<3,0,true,false,128,128><<<gA, 256, SM3>>>(xln, Wk, bk, nullptr, k,   nullptr, SQv, Dv, Dv);
    mma_nt<3,0,true,false,128,128><<<gA, 256, SM3>>>(xln, Wv, bv, nullptr, v,   nullptr, SQv, Dv, Dv);
    attn2<<<dim3(SQv/64, Hv), 256, SMAT>>>(q, k, v, amask, ctx);
    mma_nt<3,0,true,true,128,128><<<gA, 256, SM3>>>(ctx, Wo, bo, hidden, attn, nullptr, SQv, Dv, Dv);

    // ---- FFN prep ----
    ln_kernel<<<SQv, 256>>>(attn, ln2_g, ln2_b, normed);
    gemm_nt<false><<<dim3(NCv/64, LKv/64), 256>>>(Whash, W1, nullptr, projn, LKv, NCv, Dv);
    coden_kernel<<<(LTv * NCv) / 256, 256>>>();

    // ---- per-chunk LSH FFN ----
    dim3 gB(SSv/128, TPPv/64); // (8,16)
    for (int c = 0; c < 2; c++) {
        const float* hch = normed + (size_t)c * TPPv * Dv;
        const float* ach = attn   + (size_t)c * TPPv * Dv;
        float*       och = out    + (size_t)c * TPPv * Dv;

        gemm_nt<false><<<dim3(TPPv/64, LKv/64), 256>>>(Whash, hch, nullptr, projt, LKv, TPPv, Dv);
        codet_kernel<<<(LTv * TPPv) / 256, 256>>>();
        tanhpt_kernel<<<(TPPv * LKv) / 256, 256>>>();
        hist_zero<<<(LTv * NBv) / 256, 256>>>();
        hist_build<<<(LTv * TPPv) / 256, 256>>>();
        score_kernel<<<NCv / 256, 256>>>();
        select_kernel<<<1, 1024>>>();
        gather_kernel<<<(SSv * Dv) / 256, 256>>>(W1, b1);
        gatherT_kernel<<<dim3(SSv/32, Dv/32), 256>>>(W2);
        tanhpns_kernel<<<(SSv * LKv) / 256, 256>>>();

        // logits (+ fused GELU into acts)
        mma_nt<1,1,true,false,64,128><<<gB, 256, SM1>>>(hch, w1s, b1s, nullptr,
                                                        logits, acts, TPPv, SSv, Dv);
        triplet2<<<TPPv/8, 256>>>(c);
        // out = acts @ W2s + b2 + attn_residual
        mma_nt<1,0,true,true,64,128><<<dim3(Dv/128, TPPv/64), 256, SM1>>>(acts, w2sT, b2, ach,
                                                                          och, nullptr, TPPv, Dv, SSv);
    }

    // ---- scalar output ----
    trip_reduce<<<1, 1024>>>(out + (size_t)SQv * Dv);
}

// round 4
// speedup vs baseline: 1.2082x; 1.2082x over previous
#include <cuda_runtime.h>
#include <math.h>
#include <stddef.h>

// ---------------- problem constants ----------------
#define SQv   2048
#define Dv    1024
#define Hv    16
#define DHv   64
#define NCv   4096
#define LTv   16      // tables
#define KHv   8       // hash funcs per table
#define LKv   128     // LT*KH
#define NBv   256     // buckets
#define TPPv  1024
#define SSv   1024    // sample budget
#define PPv   64

// ---------------- device scratch ----------------
__device__ __align__(16) float g_xln   [SQv*Dv];
__device__ __align__(16) float g_q     [SQv*Dv];
__device__ __align__(16) float g_k     [SQv*Dv];
__device__ __align__(16) float g_v     [SQv*Dv];
__device__ __align__(16) float g_ctx   [SQv*Dv];
__device__ __align__(16) float g_attn  [SQv*Dv];
__device__ __align__(16) float g_normed[SQv*Dv];
__device__ __align__(16) float g_projn [LKv*NCv];
__device__ __align__(16) float g_projt [LKv*TPPv];
__device__ __align__(16) float g_tanhpt[TPPv*LKv];
__device__ __align__(16) float g_tanhpns[SSv*LKv];
__device__ __align__(16) float g_w1s   [SSv*Dv];
__device__ __align__(16) float g_w2sT  [Dv*SSv];
__device__ __align__(16) float g_b1s   [SSv];
__device__ __align__(16) float g_logits[TPPv*SSv];
__device__ __align__(16) float g_acts  [TPPv*SSv];
__device__ __align__(16) float g_trip  [2*TPPv];
__device__ int g_coden[LTv*NCv];
__device__ int g_codet[LTv*TPPv];
__device__ int g_hist [LTv*NBv];
__device__ int g_score[NCv];
__device__ int g_sids [SSv];

// ---------------- helpers ----------------
__device__ __forceinline__ unsigned f2tf(float x){
    unsigned u; asm("cvt.rna.tf32.f32 %0, %1;" : "=r"(u) : "f"(x)); return u;
}
__device__ __forceinline__ void mma8(float* d, const unsigned* a, const unsigned* b){
    asm volatile("mma.sync.aligned.m16n8k8.row.col.f32.tf32.tf32.f32 "
        "{%0,%1,%2,%3},{%4,%5,%6,%7},{%8,%9},{%0,%1,%2,%3};"
        : "+f"(d[0]), "+f"(d[1]), "+f"(d[2]), "+f"(d[3])
        : "r"(a[0]), "r"(a[1]), "r"(a[2]), "r"(a[3]), "r"(b[0]), "r"(b[1]));
}
__device__ __forceinline__ float gelu_exact(float x){
    return 0.5f * x * (1.f + erff(x * 0.70710678118654752f));
}

// ---------------- LayerNorm ----------------
__global__ void ln_kernel(const float* __restrict__ x, const float* __restrict__ g,
                          const float* __restrict__ b, float* __restrict__ y)
{
    int row = blockIdx.x;
    const float* xr = x + (size_t)row * Dv;
    __shared__ float red[256];
    int tid = threadIdx.x;
    float s = 0.f, ss = 0.f;
    for (int i = tid; i < Dv; i += 256) { float v = xr[i]; s += v; ss += v * v; }
    red[tid] = s; __syncthreads();
    for (int st = 128; st > 0; st >>= 1) { if (tid < st) red[tid] += red[tid + st]; __syncthreads(); }
    float mean = red[0] / Dv;
    __syncthreads();
    red[tid] = ss; __syncthreads();
    for (int st = 128; st > 0; st >>= 1) { if (tid < st) red[tid] += red[tid + st]; __syncthreads(); }
    float var = red[0] / Dv - mean * mean;
    float inv = rsqrtf(var + 1e-12f);
    float* yr = y + (size_t)row * Dv;
    for (int i = tid; i < Dv; i += 256) yr[i] = (xr[i] - mean) * inv * g[i] + b[i];
}

// ---------------- TF32 tensor-core GEMM NT ----------------
template<int SPLIT, int EPI, bool BIAS, bool RES, int BM_, int BN_>
__global__ void __launch_bounds__(256, 1)
mma_nt(const float* __restrict__ A, const float* __restrict__ B,
       const float* __restrict__ bias, const float* __restrict__ res,
       float* __restrict__ C, float* __restrict__ C2, int M, int N, int K)
{
    constexpr int BK = 32, LD = 36;
    constexpr int WTM = BM_ / 2, WTN = BN_ / 4;
    constexpr int MT = WTM / 16, NT = WTN / 8;
    extern __shared__ unsigned sm[];
    unsigned* Ah = sm;
    unsigned* Bh = Ah + BM_ * LD;
    unsigned* Al = (SPLIT == 3) ? Bh + BN_ * LD : Ah;
    unsigned* Bl = (SPLIT == 3) ? Al + BM_ * LD : Bh;

    const int tid = threadIdx.x;
    const int lane = tid & 31, wid = tid >> 5;
    const int wm = wid & 1, wn = wid >> 1;
    const int m0 = blockIdx.y * BM_, n0 = blockIdx.x * BN_;

    constexpr int PA = BM_ / 32;
    constexpr int PB = BN_ / 32;
    const int lrw = tid >> 3;
    const int lcc = (tid & 7) * 4;

    float4 pa[PA], pb[PB];
    float acc[MT][NT][4];
    #pragma unroll
    for (int i = 0; i < MT; i++)
        #pragma unroll
        for (int j = 0; j < NT; j++)
            #pragma unroll
            for (int u = 0; u < 4; u++) acc[i][j][u] = 0.f;

    #pragma unroll
    for (int p = 0; p < PA; p++)
        pa[p] = *(const float4*)(A + (size_t)(m0 + p*32 + lrw) * K + lcc);
    #pragma unroll
    for (int p = 0; p < PB; p++)
        pb[p] = *(const float4*)(B + (size_t)(n0 + p*32 + lrw) * K + lcc);

    const int ntiles = K / BK;
    for (int kt = 0; kt < ntiles; kt++) {
        __syncthreads();
        #pragma unroll
        for (int p = 0; p < PA; p++) {
            float vv[4] = {pa[p].x, pa[p].y, pa[p].z, pa[p].w};
            #pragma unroll
            for (int i = 0; i < 4; i++) {
                unsigned h = f2tf(vv[i]);
                Ah[(p*32 + lrw) * LD + lcc + i] = h;
                if (SPLIT == 3)
                    Al[(p*32 + lrw) * LD + lcc + i] = f2tf(vv[i] - __uint_as_float(h));
            }
        }
        #pragma unroll
        for (int p = 0; p < PB; p++) {
            float vv[4] = {pb[p].x, pb[p].y, pb[p].z, pb[p].w};
            #pragma unroll
            for (int i = 0; i < 4; i++) {
                unsigned h = f2tf(vv[i]);
                Bh[(p*32 + lrw) * LD + lcc + i] = h;
                if (SPLIT == 3)
                    Bl[(p*32 + lrw) * LD + lcc + i] = f2tf(vv[i] - __uint_as_float(h));
            }
        }
        __syncthreads();
        if (kt + 1 < ntiles) {
            const float* An = A + (size_t)(kt + 1) * BK;
            const float* Bn = B + (size_t)(kt + 1) * BK;
            #pragma unroll
            for (int p = 0; p < PA; p++)
                pa[p] = *(const float4*)(An + (size_t)(m0 + p*32 + lrw) * K + lcc);
            #pragma unroll
            for (int p = 0; p < PB; p++)
                pb[p] = *(const float4*)(Bn + (size_t)(n0 + p*32 + lrw) * K + lcc);
        }
        #pragma unroll
        for (int ks = 0; ks < 4; ks++) {
            unsigned ah[MT][4], al[MT][4], bh[NT][2], bl[NT][2];
            #pragma unroll
            for (int i = 0; i < MT; i++) {
                int r = wm * WTM + i * 16 + (lane >> 2);
                int c = ks * 8 + (lane & 3);
                ah[i][0] = Ah[r*LD + c];       ah[i][1] = Ah[(r+8)*LD + c];
                ah[i][2] = Ah[r*LD + c + 4];   ah[i][3] = Ah[(r+8)*LD + c + 4];
                if (SPLIT == 3) {
                    al[i][0] = Al[r*LD + c];     al[i][1] = Al[(r+8)*LD + c];
                    al[i][2] = Al[r*LD + c + 4]; al[i][3] = Al[(r+8)*LD + c + 4];
                }
            }
            #pragma unroll
            for (int j = 0; j < NT; j++) {
                int r = wn * WTN + j * 8 + (lane >> 2);
                int c = ks * 8 + (lane & 3);
                bh[j][0] = Bh[r*LD + c];  bh[j][1] = Bh[r*LD + c + 4];
                if (SPLIT == 3) {
                    bl[j][0] = Bl[r*LD + c];  bl[j][1] = Bl[r*LD + c + 4];
                }
            }
            #pragma unroll
            for (int i = 0; i < MT; i++)
                #pragma unroll
                for (int j = 0; j < NT; j++) {
                    mma8(acc[i][j], ah[i], bh[j]);
                    if (SPLIT == 3) {
                        mma8(acc[i][j], ah[i], bl[j]);
                        mma8(acc[i][j], al[i], bh[j]);
                    }
                }
        }
    }
    #pragma unroll
    for (int i = 0; i < MT; i++) {
        #pragma unroll
        for (int j = 0; j < NT; j++) {
            int r = m0 + wm * WTM + i * 16 + (lane >> 2);
            int c = n0 + wn * WTN + j * 8 + (lane & 3) * 2;
            float v00 = acc[i][j][0], v01 = acc[i][j][1];
            float v10 = acc[i][j][2], v11 = acc[i][j][3];
            if (BIAS) { float b0 = bias[c], b1 = bias[c+1]; v00 += b0; v01 += b1; v10 += b0; v11 += b1; }
            if (RES) {
                v00 += res[(size_t)r*N + c];     v01 += res[(size_t)r*N + c + 1];
                v10 += res[(size_t)(r+8)*N + c]; v11 += res[(size_t)(r+8)*N + c + 1];
            }
            *(float2*)(C + (size_t)r*N + c)     = make_float2(v00, v01);
            *(float2*)(C + (size_t)(r+8)*N + c) = make_float2(v10, v11);
            if (EPI == 1) {
                *(float2*)(C2 + (size_t)r*N + c)     = make_float2(gelu_exact(v00), gelu_exact(v01));
                *(float2*)(C2 + (size_t)(r+8)*N + c) = make_float2(gelu_exact(v10), gelu_exact(v11));
            }
        }
    }
}

// ---------------- exact-fp32 GEMM NT (hash projections only) ----------------
template<bool HAS_BIAS>
__global__ void gemm_nt(const float* __restrict__ A, const float* __restrict__ Bm,
                        const float* __restrict__ bias,
                        float* __restrict__ C, int M, int N, int Kd)
{
    __shared__ float As[16][64];
    __shared__ float Bs[16][64];
    int tid = threadIdx.x;
    int tx = tid & 15, ty = tid >> 4;
    int m0 = blockIdx.y * 64, n0 = blockIdx.x * 64;
    float acc[4][4] = {};
    for (int k0 = 0; k0 < Kd; k0 += 16) {
        int idx = tid * 4;
        int r = idx >> 4, kk = idx & 15;
        float4 av = *(const float4*)(A  + (size_t)(m0 + r) * Kd + k0 + kk);
        As[kk+0][r] = av.x; As[kk+1][r] = av.y; As[kk+2][r] = av.z; As[kk+3][r] = av.w;
        float4 bv = *(const float4*)(Bm + (size_t)(n0 + r) * Kd + k0 + kk);
        Bs[kk+0][r] = bv.x; Bs[kk+1][r] = bv.y; Bs[kk+2][r] = bv.z; Bs[kk+3][r] = bv.w;
        __syncthreads();
        #pragma unroll
        for (int q = 0; q < 16; q++) {
            float a[4], b[4];
            #pragma unroll
            for (int i = 0; i < 4; i++) a[i] = As[q][ty*4+i];
            #pragma unroll
            for (int j = 0; j < 4; j++) b[j] = Bs[q][tx*4+j];
            #pragma unroll
            for (int i = 0; i < 4; i++)
                #pragma unroll
                for (int j = 0; j < 4; j++)
                    acc[i][j] += a[i] * b[j];
        }
        __syncthreads();
    }
    #pragma unroll
    for (int i = 0; i < 4; i++) {
        int m = m0 + ty*4 + i;
        #pragma unroll
        for (int j = 0; j < 4; j++) {
            int n = n0 + tx*4 + j;
            float v = acc[i][j];
            if (HAS_BIAS) v += bias[n];
            C[(size_t)m * N + n] = v;
        }
    }
}

// ---------------- attention: 3xTF32 tensor-core flash ----------------
// Block: 64 q-rows x 1 head, 128 threads (4 warps, 16 rows/warp).
// smem: QP(hi/lo, LD=68, reused for P), K(hi/lo, LD=68), V(hi/lo, LD=72), mask.
#define LDQ 68
#define LDVt 72
__global__ void __launch_bounds__(128, 2)
attn3(const float* __restrict__ q, const float* __restrict__ k,
      const float* __restrict__ v, const float* __restrict__ mask,
      float* __restrict__ ctx)
{
    extern __shared__ unsigned sm[];
    unsigned* QPh = sm;                    // 64*68
    unsigned* QPl = QPh + 64*LDQ;
    unsigned* Kh  = QPl + 64*LDQ;
    unsigned* Kl  = Kh  + 64*LDQ;
    unsigned* Vh  = Kl  + 64*LDQ;          // [key][d], LD=72
    unsigned* Vl  = Vh  + 64*LDVt;
    float*    Ms  = (float*)(Vl + 64*LDVt);

    const int tid = threadIdx.x;
    const int lane = tid & 31, w = tid >> 5;
    const int h = blockIdx.y, q0 = blockIdx.x * 64;
    const int rr = w * 16 + (lane >> 2);   // row within block (first of pair)

    // load Q tile, split hi/lo
    for (int idx = tid; idx < 64 * 16; idx += 128) {
        int row = idx >> 4, c4 = (idx & 15) * 4;
        float4 t = *(const float4*)(q + (size_t)(q0 + row) * Dv + h * 64 + c4);
        float vv[4] = {t.x, t.y, t.z, t.w};
        #pragma unroll
        for (int u = 0; u < 4; u++) {
            unsigned hi = f2tf(vv[u]);
            QPh[row * LDQ + c4 + u] = hi;
            QPl[row * LDQ + c4 + u] = f2tf(vv[u] - __uint_as_float(hi));
        }
    }
    __syncthreads();

    // Q fragments -> registers (buffer then reused for P)
    unsigned qh[8][4], ql[8][4];
    #pragma unroll
    for (int ks = 0; ks < 8; ks++) {
        int c = ks * 8 + (lane & 3);
        qh[ks][0] = QPh[rr*LDQ + c];       qh[ks][1] = QPh[(rr+8)*LDQ + c];
        qh[ks][2] = QPh[rr*LDQ + c + 4];   qh[ks][3] = QPh[(rr+8)*LDQ + c + 4];
        ql[ks][0] = QPl[rr*LDQ + c];       ql[ks][1] = QPl[(rr+8)*LDQ + c];
        ql[ks][2] = QPl[rr*LDQ + c + 4];   ql[ks][3] = QPl[(rr+8)*LDQ + c + 4];
    }

    float o[8][4];
    #pragma unroll
    for (int j = 0; j < 8; j++)
        #pragma unroll
        for (int u = 0; u < 4; u++) o[j][u] = 0.f;
    float m0r = -1e30f, m1r = -1e30f, l0 = 0.f, l1 = 0.f;

    for (int kt = 0; kt < SQv / 64; kt++) {
        int k0 = kt * 64;
        __syncthreads();   // protect K/V/Ms from overwrite while prev PV in flight
        for (int idx = tid; idx < 64 * 16; idx += 128) {
            int row = idx >> 4, c4 = (idx & 15) * 4;
            float4 tk = *(const float4*)(k + (size_t)(k0 + row) * Dv + h * 64 + c4);
            float kv[4] = {tk.x, tk.y, tk.z, tk.w};
            #pragma unroll
            for (int u = 0; u < 4; u++) {
                unsigned hi = f2tf(kv[u]);
                Kh[row * LDQ + c4 + u] = hi;
                Kl[row * LDQ + c4 + u] = f2tf(kv[u] - __uint_as_float(hi));
            }
            float4 tv = *(const float4*)(v + (size_t)(k0 + row) * Dv + h * 64 + c4);
            float vv[4] = {tv.x, tv.y, tv.z, tv.w};
            #pragma unroll
            for (int u = 0; u < 4; u++) {
                unsigned hi = f2tf(vv[u]);
                Vh[row * LDVt + c4 + u] = hi;
                Vl[row * LDVt + c4 + u] = f2tf(vv[u] - __uint_as_float(hi));
            }
        }
        if (tid < 64) Ms[tid] = -1000.f * (1.f - mask[k0 + tid]);
        __syncthreads();

        // S = Q K^T (3x split)
        float s[8][4];
        #pragma unroll
        for (int j = 0; j < 8; j++)
            #pragma unroll
            for (int u = 0; u < 4; u++) s[j][u] = 0.f;
        #pragma unroll
        for (int ks = 0; ks < 8; ks++) {
            #pragma unroll
            for (int j = 0; j < 8; j++) {
                int r = j * 8 + (lane >> 2);
                int c = ks * 8 + (lane & 3);
                unsigned bh[2], bl[2];
                bh[0] = Kh[r*LDQ + c];  bh[1] = Kh[r*LDQ + c + 4];
                bl[0] = Kl[r*LDQ + c];  bl[1] = Kl[r*LDQ + c + 4];
                mma8(s[j], qh[ks], bh);
                mma8(s[j], qh[ks], bl);
                mma8(s[j], ql[ks], bh);
            }
        }

        // softmax (online) on fragments
        float mx0 = -1e30f, mx1 = -1e30f;
        #pragma unroll
        for (int j = 0; j < 8; j++) {
            int cb = j * 8 + (lane & 3) * 2;
            float ms0 = Ms[cb], ms1 = Ms[cb + 1];
            s[j][0] = s[j][0] * 0.125f + ms0;
            s[j][1] = s[j][1] * 0.125f + ms1;
            s[j][2] = s[j][2] * 0.125f + ms0;
            s[j][3] = s[j][3] * 0.125f + ms1;
            mx0 = fmaxf(mx0, fmaxf(s[j][0], s[j][1]));
            mx1 = fmaxf(mx1, fmaxf(s[j][2], s[j][3]));
        }
        #pragma unroll
        for (int off = 1; off < 4; off <<= 1) {
            mx0 = fmaxf(mx0, __shfl_xor_sync(0xffffffffu, mx0, off));
            mx1 = fmaxf(mx1, __shfl_xor_sync(0xffffffffu, mx1, off));
        }
        float mn0 = fmaxf(m0r, mx0), mn1 = fmaxf(m1r, mx1);
        float a0 = expf(m0r - mn0),  a1 = expf(m1r - mn1);
        m0r = mn0; m1r = mn1;
        float rs0 = 0.f, rs1 = 0.f;
        #pragma unroll
        for (int j = 0; j < 8; j++) {
            int cb = j * 8 + (lane & 3) * 2;
            float p00 = expf(s[j][0] - mn0);
            float p01 = expf(s[j][1] - mn0);
            float p10 = expf(s[j][2] - mn1);
            float p11 = expf(s[j][3] - mn1);
            rs0 += p00 + p01; rs1 += p10 + p11;
            unsigned hh;
            hh = f2tf(p00); QPh[rr*LDQ + cb]       = hh; QPl[rr*LDQ + cb]       = f2tf(p00 - __uint_as_float(hh));
            hh = f2tf(p01); QPh[rr*LDQ + cb + 1]   = hh; QPl[rr*LDQ + cb + 1]   = f2tf(p01 - __uint_as_float(hh));
            hh = f2tf(p10); QPh[(rr+8)*LDQ + cb]   = hh; QPl[(rr+8)*LDQ + cb]   = f2tf(p10 - __uint_as_float(hh));
            hh = f2tf(p11); QPh[(rr+8)*LDQ + cb+1] = hh; QPl[(rr+8)*LDQ + cb+1] = f2tf(p11 - __uint_as_float(hh));
            o[j][0] *= a0; o[j][1] *= a0; o[j][2] *= a1; o[j][3] *= a1;
        }
        #pragma unroll
        for (int off = 1; off < 4; off <<= 1) {
            rs0 += __shfl_xor_sync(0xffffffffu, rs0, off);
            rs1 += __shfl_xor_sync(0xffffffffu, rs1, off);
        }
        l0 = l0 * a0 + rs0;
        l1 = l1 * a1 + rs1;
        __syncwarp();      // P rows of this warp complete (warp-private rows)

        // O += P V (3x split). P rows are warp-private -> no block sync needed.
        #pragma unroll
        for (int ks = 0; ks < 8; ks++) {
            int c = ks * 8 + (lane & 3);
            unsigned ah[4], al[4];
            ah[0] = QPh[rr*LDQ + c];     ah[1] = QPh[(rr+8)*LDQ + c];
            ah[2] = QPh[rr*LDQ + c + 4]; ah[3] = QPh[(rr+8)*LDQ + c + 4];
            al[0] = QPl[rr*LDQ + c];     al[1] = QPl[(rr+8)*LDQ + c];
            al[2] = QPl[rr*LDQ + c + 4]; al[3] = QPl[(rr+8)*LDQ + c + 4];
            #pragma unroll
            for (int j = 0; j < 8; j++) {
                int n = j * 8 + (lane >> 2);
                unsigned bh[2], bl[2];
                bh[0] = Vh[(ks*8 + (lane&3)) * LDVt + n];
                bh[1] = Vh[(ks*8 + (lane&3) + 4) * LDVt + n];
                bl[0] = Vl[(ks*8 + (lane&3)) * LDVt + n];
                bl[1] = Vl[(ks*8 + (lane&3) + 4) * LDVt + n];
                mma8(o[j], ah, bh);
                mma8(o[j], ah, bl);
                mma8(o[j], al, bh);
            }
        }
    }

    float i0 = 1.f / l0, i1 = 1.f / l1;
    int gq = q0 + rr;
    #pragma unroll
    for (int j = 0; j < 8; j++) {
        int col = h * 64 + j * 8 + (lane & 3) * 2;
        *(float2*)(ctx + (size_t)gq * Dv + col)     = make_float2(o[j][0]*i0, o[j][1]*i0);
        *(float2*)(ctx + (size_t)(gq+8) * Dv + col) = make_float2(o[j][2]*i1, o[j][3]*i1);
    }
}

// ---------------- SimHash codes ----------------
__global__ void coden_kernel()
{
    int idx = blockIdx.x * 256 + threadIdx.x;
    if (idx >= LTv * NCv) return;
    int n = idx & (NCv - 1), l = idx >> 12;
    int code = 0;
    #pragma unroll
    for (int kk = 0; kk < KHv; kk++)
        if (g_projn[(size_t)(l * KHv + kk) * NCv + n] > 0.f) code |= (1 << kk);
    g_coden[l * NCv + n] = code;
}
__global__ void codet_kernel()
{
    int idx = blockIdx.x * 256 + threadIdx.x;
    if (idx >= LTv * TPPv) return;
    int t = idx & (TPPv - 1), l = idx >> 10;
    int code = 0;
    #pragma unroll
    for (int kk = 0; kk < KHv; kk++)
        if (g_projt[(size_t)(l * KHv + kk) * TPPv + t] > 0.f) code |= (1 << kk);
    g_codet[l * TPPv + t] = code;
}
__global__ void tanhpt_kernel()
{
    int idx = blockIdx.x * 256 + threadIdx.x;
    if (idx >= TPPv * LKv) return;
    int t = idx >> 7, lk = idx & 127;
    g_tanhpt[idx] = tanhf(g_projt[(size_t)lk * TPPv + t]);
}

// ---------------- histogram + score ----------------
__global__ void hist_zero()
{
    int i = blockIdx.x * 256 + threadIdx.x;
    if (i < LTv * NBv) g_hist[i] = 0;
}
__global__ void hist_build()
{
    int idx = blockIdx.x * 256 + threadIdx.x;
    if (idx >= LTv * TPPv) return;
    int t = idx & (TPPv - 1), l = idx >> 10;
    atomicAdd(&g_hist[l * NBv + g_codet[l * TPPv + t]], 1);
}
__global__ void score_kernel()
{
    int n = blockIdx.x * 256 + threadIdx.x;
    if (n >= NCv) return;
    int s = 0;
    #pragma unroll
    for (int l = 0; l < LTv; l++) s += g_hist[l * NBv + g_coden[l * NCv + n]];
    g_score[n] = s;
}

// ---------------- stable top-S selection ----------------
__global__ void select_kernel()
{
    __shared__ int ssc[NCv];
    __shared__ int red[1024];
    int tid = threadIdx.x;
    for (int i = tid; i < NCv; i += 1024) ssc[i] = g_score[i];
    __syncthreads();

    int lo = 0, hi = LTv * TPPv + 1;
    while (lo + 1 < hi) {
        int mid = (lo + hi) >> 1;
        int c = 0;
        for (int i = tid; i < NCv; i += 1024) c += (ssc[i] >= mid);
        red[tid] = c; __syncthreads();
        for (int st = 512; st > 0; st >>= 1) { if (tid < st) red[tid] += red[tid + st]; __syncthreads(); }
        int tot = red[0]; __syncthreads();
        if (tot >= SSv) lo = mid; else hi = mid;
    }
    int tau = lo;
    int c = 0;
    for (int i = tid; i < NCv; i += 1024) c += (ssc[i] > tau);
    red[tid] = c; __syncthreads();
    for (int st = 512; st > 0; st >>= 1) { if (tid < st) red[tid] += red[tid + st]; __syncthreads(); }
    int m = red[0];
    int need = SSv - m;
    __syncthreads();

    int base = tid * 4;
    int gtp[4], eqp[4];
    int lgt = 0, leq = 0;
    #pragma unroll
    for (int j = 0; j < 4; j++) {
        int sc = ssc[base + j];
        gtp[j] = lgt; eqp[j] = leq;
        lgt += (sc > tau); leq += (sc == tau);
    }
    red[tid] = (lgt << 16) | leq; __syncthreads();
    for (int off = 1; off < 1024; off <<= 1) {
        int vv = (tid >= off) ? red[tid - off] : 0;
        __syncthreads();
        red[tid] += vv;
        __syncthreads();
    }
    int excl = (tid == 0) ? 0 : red[tid - 1];
    int egt = excl >> 16, eeq = excl & 0xffff;
    #pragma unroll
    for (int j = 0; j < 4; j++) {
        int sc = ssc[base + j];
        if (sc > tau)                                g_sids[egt + gtp[j]] = base + j;
        else if (sc == tau && (eeq + eqp[j]) < need) g_sids[m + eeq + eqp[j]] = base + j;
    }
}

// ---------------- gathers ----------------
__global__ void gather_kernel(const float* __restrict__ W1, const float* __restrict__ b1)
{
    int idx = blockIdx.x * 256 + threadIdx.x;
    if (idx >= SSv * Dv) return;
    int s = idx >> 10, dcol = idx & 1023;
    int row = g_sids[s];
    g_w1s[idx] = W1[(size_t)row * Dv + dcol];
    if (dcol == 0) g_b1s[s] = b1[row];
}
__global__ void gatherT_kernel(const float* __restrict__ W2)
{
    __shared__ float tile[32][33];
    int s0 = blockIdx.x * 32, d0 = blockIdx.y * 32;
    int tx = threadIdx.x & 31, ty8 = threadIdx.x >> 5;
    for (int r = ty8; r < 32; r += 8) {
        int row = g_sids[s0 + r];
        tile[r][tx] = W2[(size_t)row * Dv + d0 + tx];
    }
    __syncthreads();
    for (int r = ty8; r < 32; r += 8)
        g_w2sT[(size_t)(d0 + r) * SSv + s0 + tx] = tile[tx][r];
}
__global__ void tanhpns_kernel()
{
    int idx = blockIdx.x * 256 + threadIdx.x;
    if (idx >= SSv * LKv) return;
    int s = idx >> 7, lk = idx & 127;
    g_tanhpns[idx] = tanhf(g_projn[(size_t)lk * NCv + g_sids[s]]);
}

// ---------------- triplet loss (warp per token, shuffle-only) ----------------
__global__ void __launch_bounds__(256)
triplet2(int chunk)
{
    __shared__ float vals[8][1024];
    int w = threadIdx.x >> 5, lane = threadIdx.x & 31;
    int t = blockIdx.x * 8 + w;
    const float* lrow = g_logits + (size_t)t * SSv;

    float apos = 0.f, aneg = 0.f;
    for (int phase = 0; phase < 2; phase++) {
        for (int i = lane; i < 256; i += 32)
            ((float4*)vals[w])[i] = ((const float4*)lrow)[i];
        __syncwarp();
        float sv[4] = {0.f, 0.f, 0.f, 0.f};
        for (int it = 0; it < PPv; it++) {
            float bv = (phase == 0) ? -1e30f : 1e30f;
            int bi = 1 << 30;
            #pragma unroll
            for (int qd = 0; qd < 32; qd++) {
                int i = lane + (qd << 5);
                float x = vals[w][i];
                bool better = (phase == 0) ? (x > bv) : (x < bv);
                if (better) { bv = x; bi = i; }
            }
            #pragma unroll
            for (int off = 16; off > 0; off >>= 1) {
                float ov = __shfl_xor_sync(0xffffffffu, bv, off);
                int   oi = __shfl_xor_sync(0xffffffffu, bi, off);
                bool take = (phase == 0)
                    ? (ov > bv || (ov == bv && oi < bi))
                    : (ov < bv || (ov == bv && oi < bi));
                if (take) { bv = ov; bi = oi; }
            }
            #pragma unroll
            for (int c2 = 0; c2 < 4; c2++)
                sv[c2] += g_tanhpns[(size_t)bi * LKv + lane + 32 * c2];
            if (lane == 0) vals[w][bi] = (phase == 0) ? -1e30f : 1e30f;
            __syncwarp();
        }
        float a = 0.f;
        #pragma unroll
        for (int c2 = 0; c2 < 4; c2++)
            a += sv[c2] * g_tanhpt[(size_t)t * LKv + lane + 32 * c2];
        #pragma unroll
        for (int off = 16; off > 0; off >>= 1)
            a += __shfl_xor_sync(0xffffffffu, a, off);
        a *= 1.0f / (128.0f * 64.0f);
        if (phase == 0) apos = a; else aneg = a;
    }
    if (lane == 0) g_trip[chunk * TPPv + t] = fmaxf(aneg - apos + 0.5f, 0.f);
}

__global__ void trip_reduce(float* __restrict__ outp)
{
    __shared__ float red[1024];
    int tid = threadIdx.x;
    red[tid] = g_trip[tid] + g_trip[tid + 1024];
    __syncthreads();
    for (int st = 512; st > 0; st >>= 1) { if (tid < st) red[tid] += red[tid + st]; __syncthreads(); }
    if (tid == 0) *outp = red[0] * (1.0f / 2048.0f);
}

// ---------------- host ----------------
extern "C" void kernel_launch(void* const* d_in, const int* in_sizes, int n_in,
                              void* d_out, int out_size)
{
    const float* hidden = (const float*)d_in[0];
    const float* amask  = (const float*)d_in[1];
    const float* ln1_g  = (const float*)d_in[2];
    const float* ln1_b  = (const float*)d_in[3];
    const float* Wq     = (const float*)d_in[4];
    const float* bq     = (const float*)d_in[5];
    const float* Wk     = (const float*)d_in[6];
    const float* bk     = (const float*)d_in[7];
    const float* Wv     = (const float*)d_in[8];
    const float* bv     = (const float*)d_in[9];
    const float* Wo     = (const float*)d_in[10];
    const float* bo     = (const float*)d_in[11];
    const float* ln2_g  = (const float*)d_in[12];
    const float* ln2_b  = (const float*)d_in[13];
    const float* W1     = (const float*)d_in[14];
    const float* b1     = (const float*)d_in[15];
    const float* Whash  = (const float*)d_in[16];
    const float* W2     = (const float*)d_in[17];
    const float* b2     = (const float*)d_in[18];
    float* out = (float*)d_out;

    float *xln, *q, *k, *v, *ctx, *attn, *normed, *projn, *projt;
    float *w1s, *w2sT, *b1s, *logits, *acts;
    cudaGetSymbolAddress((void**)&xln,    g_xln);
    cudaGetSymbolAddress((void**)&q,      g_q);
    cudaGetSymbolAddress((void**)&k,      g_k);
    cudaGetSymbolAddress((void**)&v,      g_v);
    cudaGetSymbolAddress((void**)&ctx,    g_ctx);
    cudaGetSymbolAddress((void**)&attn,   g_attn);
    cudaGetSymbolAddress((void**)&normed, g_normed);
    cudaGetSymbolAddress((void**)&projn,  g_projn);
    cudaGetSymbolAddress((void**)&projt,  g_projt);
    cudaGetSymbolAddress((void**)&w1s,    g_w1s);
    cudaGetSymbolAddress((void**)&w2sT,   g_w2sT);
    cudaGetSymbolAddress((void**)&b1s,    g_b1s);
    cudaGetSymbolAddress((void**)&logits, g_logits);
    cudaGetSymbolAddress((void**)&acts,   g_acts);

    const int SM3  = (128 + 128) * 36 * 4 * 2;   // 73728
    const int SM1  = (64 + 128) * 36 * 4;        // 27648
    const int SMAT = (4*64*LDQ + 2*64*LDVt) * 4 + 64*4;   // 106752
    cudaFuncSetAttribute((const void*)mma_nt<3,0,true,false,128,128>,
                         cudaFuncAttributeMaxDynamicSharedMemorySize, SM3);
    cudaFuncSetAttribute((const void*)mma_nt<3,0,true,true,128,128>,
                         cudaFuncAttributeMaxDynamicSharedMemorySize, SM3);
    cudaFuncSetAttribute((const void*)mma_nt<1,1,true,false,64,128>,
                         cudaFuncAttributeMaxDynamicSharedMemorySize, SM1);
    cudaFuncSetAttribute((const void*)mma_nt<1,0,true,true,64,128>,
                         cudaFuncAttributeMaxDynamicSharedMemorySize, SM1);
    cudaFuncSetAttribute((const void*)attn3,
                         cudaFuncAttributeMaxDynamicSharedMemorySize, SMAT);

    // ---- attention path ----
    ln_kernel<<<SQv, 256>>>(hidden, ln1_g, ln1_b, xln);
    dim3 gA(Dv/128, SQv/128);
    mma_nt<3,0,true,false,128,128><<<gA, 256, SM3>>>(xln, Wq, bq, nullptr, q,   nullptr, SQv, Dv, Dv);
    mma_nt<3,0,true,false,128,128><<<gA, 256, SM3>>>(xln, Wk, bk, nullptr, k,   nullptr, SQv, Dv, Dv);
    mma_nt<3,0,true,false,128,128><<<gA, 256, SM3>>>(xln, Wv, bv, nullptr, v,   nullptr, SQv, Dv, Dv);
    attn3<<<dim3(SQv/64, Hv), 128, SMAT>>>(q, k, v, amask, ctx);
    mma_nt<3,0,true,true,128,128><<<gA, 256, SM3>>>(ctx, Wo, bo, hidden, attn, nullptr, SQv, Dv, Dv);

    // ---- FFN prep ----
    ln_kernel<<<SQv, 256>>>(attn, ln2_g, ln2_b, normed);
    gemm_nt<false><<<dim3(NCv/64, LKv/64), 256>>>(Whash, W1, nullptr, projn, LKv, NCv, Dv);
    coden_kernel<<<(LTv * NCv) / 256, 256>>>();

    // ---- per-chunk LSH FFN ----
    dim3 gB(SSv/128, TPPv/64);
    for (int c = 0; c < 2; c++) {
        const float* hch = normed + (size_t)c * TPPv * Dv;
        const float* ach = attn   + (size_t)c * TPPv * Dv;
        float*       och = out    + (size_t)c * TPPv * Dv;

        gemm_nt<false><<<dim3(TPPv/64, LKv/64), 256>>>(Whash, hch, nullptr, projt, LKv, TPPv, Dv);
        codet_kernel<<<(LTv * TPPv) / 256, 256>>>();
        tanhpt_kernel<<<(TPPv * LKv) / 256, 256>>>();
        hist_zero<<<(LTv * NBv) / 256, 256>>>();
        hist_build<<<(LTv * TPPv) / 256, 256>>>();
        score_kernel<<<NCv / 256, 256>>>();
        select_kernel<<<1, 1024>>>();
        gather_kernel<<<(SSv * Dv) / 256, 256>>>(W1, b1);
        gatherT_kernel<<<dim3(SSv/32, Dv/32), 256>>>(W2);
        tanhpns_kernel<<<(SSv * LKv) / 256, 256>>>();

        mma_nt<1,1,true,false,64,128><<<gB, 256, SM1>>>(hch, w1s, b1s, nullptr,
                                                        logits, acts, TPPv, SSv, Dv);
        triplet2<<<TPPv/8, 256>>>(c);
        mma_nt<1,0,true,true,64,128><<<dim3(Dv/128, TPPv/64), 256, SM1>>>(acts, w2sT, b2, ach,
                                                                          och, nullptr, TPPv, Dv, SSv);
    }

    // ---- scalar output ----
    trip_reduce<<<1, 1024>>>(out + (size_t)SQv * Dv);
}